// round 1
// baseline (speedup 1.0000x reference)
#include <cuda_runtime.h>
#include <cstddef>

#define NN 100000
#define IN_DIM 256
#define H_DIM 128
#define C_DIM 40

// Scratch (device globals — no allocation allowed)
__device__ float g_h1[(size_t)NN * H_DIM];   // relu(X@W1)
__device__ float g_h2[(size_t)NN * C_DIM];   // h1@W2
__device__ float g_z1[(size_t)NN * C_DIM];   // first propagation

// ---------------------------------------------------------------------------
// GEMM1 + relu: g_h1 = relu(A[M,256] @ W1[256,128])
// 128x128 tile, BK=8, 256 threads, 8x8 per-thread microtile.
// ---------------------------------------------------------------------------
__global__ __launch_bounds__(256) void gemm1_relu_kernel(
    const float* __restrict__ A, const float* __restrict__ B, int M) {
    constexpr int BM = 128, BN = 128, BK = 8, TM = 8, TN = 8;
    __shared__ float As[BK][BM];
    __shared__ float Bs[BK][BN];

    const int tid = threadIdx.x;
    const int blockRow = blockIdx.x;

    const int threadRow = tid / 16;        // 0..15
    const int threadCol = tid % 16;        // 0..15
    const int innerRowA = tid / 2;         // 0..127
    const int innerColA = (tid % 2) * 4;   // 0 or 4
    const int innerRowB = tid / 32;        // 0..7
    const int innerColB = (tid % 32) * 4;  // 0..124

    float acc[TM][TN];
    #pragma unroll
    for (int i = 0; i < TM; i++)
        #pragma unroll
        for (int j = 0; j < TN; j++) acc[i][j] = 0.0f;

    float regM[TM], regN[TN];

    for (int k0 = 0; k0 < IN_DIM; k0 += BK) {
        // Load A tile (transposed into As)
        const int arow = blockRow * BM + innerRowA;
        float4 a4 = make_float4(0.f, 0.f, 0.f, 0.f);
        if (arow < M)
            a4 = *reinterpret_cast<const float4*>(A + (size_t)arow * IN_DIM + k0 + innerColA);
        As[innerColA + 0][innerRowA] = a4.x;
        As[innerColA + 1][innerRowA] = a4.y;
        As[innerColA + 2][innerRowA] = a4.z;
        As[innerColA + 3][innerRowA] = a4.w;
        // Load B tile
        float4 b4 = *reinterpret_cast<const float4*>(
            B + (size_t)(k0 + innerRowB) * H_DIM + innerColB);
        *reinterpret_cast<float4*>(&Bs[innerRowB][innerColB]) = b4;
        __syncthreads();

        #pragma unroll
        for (int k = 0; k < BK; k++) {
            #pragma unroll
            for (int i = 0; i < TM; i++) regM[i] = As[k][threadRow * TM + i];
            #pragma unroll
            for (int j = 0; j < TN; j++) regN[j] = Bs[k][threadCol * TN + j];
            #pragma unroll
            for (int i = 0; i < TM; i++)
                #pragma unroll
                for (int j = 0; j < TN; j++)
                    acc[i][j] += regM[i] * regN[j];
        }
        __syncthreads();
    }

    // Epilogue: relu + store
    #pragma unroll
    for (int i = 0; i < TM; i++) {
        const int row = blockRow * BM + threadRow * TM + i;
        if (row < M) {
            #pragma unroll
            for (int j = 0; j < TN; j += 4) {
                float4 v;
                v.x = fmaxf(acc[i][j + 0], 0.f);
                v.y = fmaxf(acc[i][j + 1], 0.f);
                v.z = fmaxf(acc[i][j + 2], 0.f);
                v.w = fmaxf(acc[i][j + 3], 0.f);
                *reinterpret_cast<float4*>(
                    g_h1 + (size_t)row * H_DIM + threadCol * TN + j) = v;
            }
        }
    }
}

// ---------------------------------------------------------------------------
// GEMM2: g_h2 = g_h1[M,128] @ W2[128,40]
// Block handles 32 rows; W2 fully in smem; H tile padded (stride 129).
// Thread layout: r = tid%32 (row), cg = tid/32 (0..7) -> cols [cg*5, cg*5+5)
// ---------------------------------------------------------------------------
__global__ __launch_bounds__(256) void gemm2_kernel(
    const float* __restrict__ W2, int M) {
    __shared__ float Ws[H_DIM][C_DIM];     // 20 KB
    __shared__ float Hs[32][H_DIM + 1];    // 16.5 KB

    const int tid = threadIdx.x;
    const int rowBase = blockIdx.x * 32;

    // Load W2 (5120 floats, 20 per thread)
    for (int i = tid; i < H_DIM * C_DIM; i += 256)
        Ws[i / C_DIM][i % C_DIM] = W2[i];

    // Load 32x128 H tile (coalesced float4 from global, scalar to padded smem)
    for (int i = tid; i < 32 * H_DIM / 4; i += 256) {
        const int r = (i * 4) / H_DIM;
        const int c = (i * 4) % H_DIM;
        float4 v = make_float4(0.f, 0.f, 0.f, 0.f);
        if (rowBase + r < M)
            v = *reinterpret_cast<const float4*>(g_h1 + (size_t)(rowBase + r) * H_DIM + c);
        Hs[r][c + 0] = v.x; Hs[r][c + 1] = v.y; Hs[r][c + 2] = v.z; Hs[r][c + 3] = v.w;
    }
    __syncthreads();

    const int r = tid % 32;
    const int cbase = (tid / 32) * 5;
    float acc[5] = {0.f, 0.f, 0.f, 0.f, 0.f};
    #pragma unroll 8
    for (int k = 0; k < H_DIM; k++) {
        const float h = Hs[r][k];
        #pragma unroll
        for (int j = 0; j < 5; j++) acc[j] += h * Ws[k][cbase + j];
    }

    const int row = rowBase + r;
    if (row < M) {
        #pragma unroll
        for (int j = 0; j < 5; j++)
            g_h2[(size_t)row * C_DIM + cbase + j] = acc[j];
    }
}

// ---------------------------------------------------------------------------
// SPMM: out[dst] += val * x[src], COO with SORTED dst.
// blockDim (40, 8). Each block stages 512 edges' metadata in smem.
// Each y-group handles 64 edges; per-thread register accumulation across
// equal-dst runs, flushing with atomicAdd only on dst change.
// ---------------------------------------------------------------------------
#define SPMM_CHUNK 512
#define SPMM_EPW 64

__global__ __launch_bounds__(320) void spmm_kernel(
    const int* __restrict__ src, const int* __restrict__ dst,
    const float* __restrict__ val, const float* __restrict__ x,
    float* __restrict__ out, int E) {
    __shared__ int   s_src[SPMM_CHUNK];
    __shared__ int   s_dst[SPMM_CHUNK];
    __shared__ float s_val[SPMM_CHUNK];

    const int tid = threadIdx.y * 40 + threadIdx.x;
    const int e0 = blockIdx.x * SPMM_CHUNK;
    const int cnt = min(SPMM_CHUNK, E - e0);

    for (int i = tid; i < cnt; i += 320) {
        s_src[i] = src[e0 + i];
        s_dst[i] = dst[e0 + i];
        s_val[i] = val[e0 + i];
    }
    __syncthreads();

    const int c = threadIdx.x;         // column 0..39
    const int begin = threadIdx.y * SPMM_EPW;
    const int end = min(begin + SPMM_EPW, cnt);
    if (begin < end) {
        float acc = 0.f;
        int prev = s_dst[begin];
        for (int i = begin; i < end; i++) {
            const int d = s_dst[i];
            if (d != prev) {
                atomicAdd(out + (size_t)prev * C_DIM + c, acc);
                acc = 0.f;
                prev = d;
            }
            acc += s_val[i] * __ldg(x + (size_t)s_src[i] * C_DIM + c);
        }
        atomicAdd(out + (size_t)prev * C_DIM + c, acc);
    }
}

// ---------------------------------------------------------------------------
// Zero fill
// ---------------------------------------------------------------------------
__global__ void zero_kernel(float4* __restrict__ p, int n4) {
    const int i = blockIdx.x * blockDim.x + threadIdx.x;
    if (i < n4) p[i] = make_float4(0.f, 0.f, 0.f, 0.f);
}

extern "C" void kernel_launch(void* const* d_in, const int* in_sizes, int n_in,
                              void* d_out, int out_size) {
    const float* features = (const float*)d_in[0];
    const float* W1       = (const float*)d_in[1];
    const float* W2       = (const float*)d_in[2];
    const int*   edge_src = (const int*)d_in[3];
    const int*   edge_dst = (const int*)d_in[4];
    const float* edge_val = (const float*)d_in[5];
    float* out = (float*)d_out;

    const int M = in_sizes[0] / IN_DIM;   // 100000
    const int E = in_sizes[3];            // 1600000

    float *p_h2, *p_z1;
    cudaGetSymbolAddress((void**)&p_h2, g_h2);
    cudaGetSymbolAddress((void**)&p_z1, g_z1);

    // 1) h1 = relu(X @ W1)
    gemm1_relu_kernel<<<(M + 127) / 128, 256>>>(features, W1, M);
    // 2) h2 = h1 @ W2
    gemm2_kernel<<<(M + 31) / 32, 256>>>(W2, M);

    const int n4 = M * C_DIM / 4;  // 1,000,000 float4
    // 3) z1 = A @ h2
    zero_kernel<<<(n4 + 255) / 256, 256>>>((float4*)p_z1, n4);
    spmm_kernel<<<(E + SPMM_CHUNK - 1) / SPMM_CHUNK, dim3(40, 8)>>>(
        edge_src, edge_dst, edge_val, p_h2, p_z1, E);
    // 4) out = A @ z1
    zero_kernel<<<(n4 + 255) / 256, 256>>>((float4*)out, n4);
    spmm_kernel<<<(E + SPMM_CHUNK - 1) / SPMM_CHUNK, dim3(40, 8)>>>(
        edge_src, edge_dst, edge_val, p_z1, out, E);
}

// round 2
// speedup vs baseline: 1.0976x; 1.0976x over previous
#include <cuda_runtime.h>
#include <cstddef>

#define NN 100000
#define IN_DIM 256
#define H_DIM 128
#define C_DIM 40

// Scratch (device globals — no allocation allowed)
__device__ float g_h1[(size_t)NN * H_DIM];   // relu(X@W1)
__device__ float g_h2[(size_t)NN * C_DIM];   // h1@W2
__device__ float g_z1[(size_t)NN * C_DIM];   // first propagation

// ---------------------------------------------------------------------------
// GEMM1 + relu: g_h1 = relu(A[M,256] @ W1[256,128])
// 128x128 tile, BK=16, double-buffered smem, 256 threads, 8x8 microtile.
// ---------------------------------------------------------------------------
__global__ __launch_bounds__(256) void gemm1_relu_kernel(
    const float* __restrict__ A, const float* __restrict__ B, int M) {
    constexpr int BM = 128, BN = 128, BK = 16, TM = 8, TN = 8;
    __shared__ float As[2][BK][BM];   // 16 KB
    __shared__ float Bs[2][BK][BN];   // 16 KB

    const int tid = threadIdx.x;
    const int blockRow = blockIdx.x;

    const int threadRow = tid / 16;        // 0..15
    const int threadCol = tid % 16;        // 0..15

    // A tile loads: 128 rows x 16 cols = 512 float4; 2 per thread
    const int aRow0 = tid / 4;             // 0..63
    const int aCol  = (tid % 4) * 4;       // 0,4,8,12
    // B tile loads: 16 rows x 128 cols = 512 float4; 2 per thread
    const int bRow0 = tid / 32;            // 0..7
    const int bCol  = (tid % 32) * 4;      // 0..124

    float acc[TM][TN];
    #pragma unroll
    for (int i = 0; i < TM; i++)
        #pragma unroll
        for (int j = 0; j < TN; j++) acc[i][j] = 0.0f;

    // ---- prologue: load k-tile 0 into buffer 0 ----
    #pragma unroll
    for (int i = 0; i < 2; i++) {
        const int r = aRow0 + i * 64;
        const int arow = blockRow * BM + r;
        float4 a4 = make_float4(0.f, 0.f, 0.f, 0.f);
        if (arow < M)
            a4 = *reinterpret_cast<const float4*>(A + (size_t)arow * IN_DIM + aCol);
        As[0][aCol + 0][r] = a4.x;
        As[0][aCol + 1][r] = a4.y;
        As[0][aCol + 2][r] = a4.z;
        As[0][aCol + 3][r] = a4.w;
        const int br = bRow0 + i * 8;
        *reinterpret_cast<float4*>(&Bs[0][br][bCol]) =
            *reinterpret_cast<const float4*>(B + (size_t)br * H_DIM + bCol);
    }
    __syncthreads();

    int cur = 0;
    constexpr int NKT = IN_DIM / BK;   // 16
    for (int kt = 0; kt < NKT; kt++) {
        float4 a_pref[2], b_pref[2];
        if (kt < NKT - 1) {
            const int k0 = (kt + 1) * BK;
            #pragma unroll
            for (int i = 0; i < 2; i++) {
                const int arow = blockRow * BM + aRow0 + i * 64;
                a_pref[i] = make_float4(0.f, 0.f, 0.f, 0.f);
                if (arow < M)
                    a_pref[i] = *reinterpret_cast<const float4*>(
                        A + (size_t)arow * IN_DIM + k0 + aCol);
                b_pref[i] = *reinterpret_cast<const float4*>(
                    B + (size_t)(k0 + bRow0 + i * 8) * H_DIM + bCol);
            }
        }

        #pragma unroll
        for (int k = 0; k < BK; k++) {
            float regM[TM], regN[TN];
            *reinterpret_cast<float4*>(&regM[0]) =
                *reinterpret_cast<const float4*>(&As[cur][k][threadRow * TM]);
            *reinterpret_cast<float4*>(&regM[4]) =
                *reinterpret_cast<const float4*>(&As[cur][k][threadRow * TM + 4]);
            *reinterpret_cast<float4*>(&regN[0]) =
                *reinterpret_cast<const float4*>(&Bs[cur][k][threadCol * TN]);
            *reinterpret_cast<float4*>(&regN[4]) =
                *reinterpret_cast<const float4*>(&Bs[cur][k][threadCol * TN + 4]);
            #pragma unroll
            for (int i = 0; i < TM; i++)
                #pragma unroll
                for (int j = 0; j < TN; j++)
                    acc[i][j] += regM[i] * regN[j];
        }

        if (kt < NKT - 1) {
            const int nxt = 1 - cur;
            #pragma unroll
            for (int i = 0; i < 2; i++) {
                const int r = aRow0 + i * 64;
                As[nxt][aCol + 0][r] = a_pref[i].x;
                As[nxt][aCol + 1][r] = a_pref[i].y;
                As[nxt][aCol + 2][r] = a_pref[i].z;
                As[nxt][aCol + 3][r] = a_pref[i].w;
                *reinterpret_cast<float4*>(&Bs[nxt][bRow0 + i * 8][bCol]) = b_pref[i];
            }
            __syncthreads();
            cur = nxt;
        }
    }

    // Epilogue: relu + store
    #pragma unroll
    for (int i = 0; i < TM; i++) {
        const int row = blockRow * BM + threadRow * TM + i;
        if (row < M) {
            #pragma unroll
            for (int j = 0; j < TN; j += 4) {
                float4 v;
                v.x = fmaxf(acc[i][j + 0], 0.f);
                v.y = fmaxf(acc[i][j + 1], 0.f);
                v.z = fmaxf(acc[i][j + 2], 0.f);
                v.w = fmaxf(acc[i][j + 3], 0.f);
                *reinterpret_cast<float4*>(
                    g_h1 + (size_t)row * H_DIM + threadCol * TN + j) = v;
            }
        }
    }
}

// ---------------------------------------------------------------------------
// GEMM2: g_h2 = g_h1[M,128] @ W2[128,40]
// ---------------------------------------------------------------------------
__global__ __launch_bounds__(256) void gemm2_kernel(
    const float* __restrict__ W2, int M) {
    __shared__ float Ws[H_DIM][C_DIM];     // 20 KB
    __shared__ float Hs[32][H_DIM + 1];    // 16.5 KB

    const int tid = threadIdx.x;
    const int rowBase = blockIdx.x * 32;

    for (int i = tid; i < H_DIM * C_DIM; i += 256)
        Ws[i / C_DIM][i % C_DIM] = W2[i];

    for (int i = tid; i < 32 * H_DIM / 4; i += 256) {
        const int r = (i * 4) / H_DIM;
        const int c = (i * 4) % H_DIM;
        float4 v = make_float4(0.f, 0.f, 0.f, 0.f);
        if (rowBase + r < M)
            v = *reinterpret_cast<const float4*>(g_h1 + (size_t)(rowBase + r) * H_DIM + c);
        Hs[r][c + 0] = v.x; Hs[r][c + 1] = v.y; Hs[r][c + 2] = v.z; Hs[r][c + 3] = v.w;
    }
    __syncthreads();

    const int r = tid % 32;
    const int cbase = (tid / 32) * 5;
    float acc[5] = {0.f, 0.f, 0.f, 0.f, 0.f};
    #pragma unroll 8
    for (int k = 0; k < H_DIM; k++) {
        const float h = Hs[r][k];
        #pragma unroll
        for (int j = 0; j < 5; j++) acc[j] += h * Ws[k][cbase + j];
    }

    const int row = rowBase + r;
    if (row < M) {
        #pragma unroll
        for (int j = 0; j < 5; j++)
            g_h2[(size_t)row * C_DIM + cbase + j] = acc[j];
    }
}

// ---------------------------------------------------------------------------
// SPMM: out[dst] += val * x[src], COO with SORTED dst.
// 320 threads = 32 groups x 10 lanes. Each lane owns a float4 (4 columns).
// Each group handles 64 edges; register accumulation across equal-dst runs,
// flushing with atomicAdd only on dst change.
// ---------------------------------------------------------------------------
#define SPMM_CHUNK 2048
#define SPMM_G 64

__global__ __launch_bounds__(320) void spmm_kernel(
    const int* __restrict__ src, const int* __restrict__ dst,
    const float* __restrict__ val, const float* __restrict__ x,
    float* __restrict__ out, int E) {
    __shared__ int   s_src[SPMM_CHUNK];
    __shared__ int   s_dst[SPMM_CHUNK];
    __shared__ float s_val[SPMM_CHUNK];

    const int tid = threadIdx.x;
    const int e0 = blockIdx.x * SPMM_CHUNK;
    const int cnt = min(SPMM_CHUNK, E - e0);

    for (int i = tid; i < cnt; i += 320) {
        s_src[i] = src[e0 + i];
        s_dst[i] = dst[e0 + i];
        s_val[i] = val[e0 + i];
    }
    __syncthreads();

    const int g = tid / 10;            // group 0..31
    const int lane = tid % 10;         // float4 lane 0..9
    const int begin = g * SPMM_G;
    const int end = min(begin + SPMM_G, cnt);
    if (begin < end) {
        float ax = 0.f, ay = 0.f, az = 0.f, aw = 0.f;
        int prev = s_dst[begin];
        for (int i = begin; i < end; i++) {
            const int d = s_dst[i];
            if (d != prev) {
                float* o = out + (size_t)prev * C_DIM + lane * 4;
                atomicAdd(o + 0, ax); atomicAdd(o + 1, ay);
                atomicAdd(o + 2, az); atomicAdd(o + 3, aw);
                ax = ay = az = aw = 0.f;
                prev = d;
            }
            const float v = s_val[i];
            const float4 xv = *reinterpret_cast<const float4*>(
                x + (size_t)s_src[i] * C_DIM + lane * 4);
            ax = fmaf(v, xv.x, ax); ay = fmaf(v, xv.y, ay);
            az = fmaf(v, xv.z, az); aw = fmaf(v, xv.w, aw);
        }
        float* o = out + (size_t)prev * C_DIM + lane * 4;
        atomicAdd(o + 0, ax); atomicAdd(o + 1, ay);
        atomicAdd(o + 2, az); atomicAdd(o + 3, aw);
    }
}

// ---------------------------------------------------------------------------
// Zero fill
// ---------------------------------------------------------------------------
__global__ void zero_kernel(float4* __restrict__ p, int n4) {
    const int i = blockIdx.x * blockDim.x + threadIdx.x;
    if (i < n4) p[i] = make_float4(0.f, 0.f, 0.f, 0.f);
}

extern "C" void kernel_launch(void* const* d_in, const int* in_sizes, int n_in,
                              void* d_out, int out_size) {
    const float* features = (const float*)d_in[0];
    const float* W1       = (const float*)d_in[1];
    const float* W2       = (const float*)d_in[2];
    const int*   edge_src = (const int*)d_in[3];
    const int*   edge_dst = (const int*)d_in[4];
    const float* edge_val = (const float*)d_in[5];
    float* out = (float*)d_out;

    const int M = in_sizes[0] / IN_DIM;   // 100000
    const int E = in_sizes[3];            // 1600000

    float *p_h2, *p_z1;
    cudaGetSymbolAddress((void**)&p_h2, g_h2);
    cudaGetSymbolAddress((void**)&p_z1, g_z1);

    // 1) h1 = relu(X @ W1)
    gemm1_relu_kernel<<<(M + 127) / 128, 256>>>(features, W1, M);
    // 2) h2 = h1 @ W2
    gemm2_kernel<<<(M + 31) / 32, 256>>>(W2, M);

    const int n4 = M * C_DIM / 4;  // 1,000,000 float4
    // 3) z1 = A @ h2
    zero_kernel<<<(n4 + 255) / 256, 256>>>((float4*)p_z1, n4);
    spmm_kernel<<<(E + SPMM_CHUNK - 1) / SPMM_CHUNK, 320>>>(
        edge_src, edge_dst, edge_val, p_h2, p_z1, E);
    // 4) out = A @ z1
    zero_kernel<<<(n4 + 255) / 256, 256>>>((float4*)out, n4);
    spmm_kernel<<<(E + SPMM_CHUNK - 1) / SPMM_CHUNK, 320>>>(
        edge_src, edge_dst, edge_val, p_z1, out, E);
}

// round 3
// speedup vs baseline: 2.1015x; 1.9146x over previous
#include <cuda_runtime.h>
#include <cstddef>
#include <cstdint>

#define NN 100000
#define IN_DIM 256
#define H_DIM 128
#define C_DIM 40

// Scratch (device globals — no allocation allowed)
__device__ float g_h2[(size_t)NN * C_DIM];   // (relu(X@W1))@W2
__device__ float g_z1[(size_t)NN * C_DIM];   // first propagation

// ---------------------------------------------------------------------------
// tf32 helpers
// ---------------------------------------------------------------------------
__device__ __forceinline__ float tf32r(float x) {
    uint32_t u;
    asm("cvt.rna.tf32.f32 %0, %1;" : "=r"(u) : "f"(x));
    return __uint_as_float(u);
}

__device__ __forceinline__ void mma_tf32(float* c, const uint32_t* a,
                                         uint32_t b0, uint32_t b1) {
    asm volatile(
        "mma.sync.aligned.m16n8k8.row.col.f32.tf32.tf32.f32 "
        "{%0,%1,%2,%3}, {%4,%5,%6,%7}, {%8,%9}, {%0,%1,%2,%3};\n"
        : "+f"(c[0]), "+f"(c[1]), "+f"(c[2]), "+f"(c[3])
        : "r"(a[0]), "r"(a[1]), "r"(a[2]), "r"(a[3]), "r"(b0), "r"(b1));
}

// ---------------------------------------------------------------------------
// Fused MLP: g_h2 = relu(X[M,256] @ W1[256,128]) @ W2[128,40]
// 256 threads (8 warps). Stage 1: 128x128 h1 tile via tf32 mma, K=256,
// BK=32 double-buffered. Stage 2: h1_tile(smem) @ W2(smem), K=128 in-block.
//
// Dynamic smem layout (union of two stages):
//   stage1: As[2][128][36] (9216 f) | Bs[2][32][132] (8448 f)   = 70656 B
//   stage2: H[128][132]    (16896 f)| Ws[128][44]    (5632 f)   = 90112 B
// ---------------------------------------------------------------------------
#define S1_AS_STRIDE 36
#define S1_BS_STRIDE 132
#define S2_H_STRIDE 132
#define S2_W_STRIDE 44
#define FUSED_SMEM_BYTES 90112

extern __shared__ float sm[];

__global__ __launch_bounds__(256) void fused_mlp_kernel(
    const float* __restrict__ A, const float* __restrict__ W1,
    const float* __restrict__ W2, int M) {
    const int tid = threadIdx.x;
    const int lane = tid & 31;
    const int wid = tid >> 5;
    const int blockRow = blockIdx.x;

    float* As = sm;                       // [2][128][36]
    float* Bs = sm + 2 * 128 * S1_AS_STRIDE;  // [2][32][132]

    const int warp_m = wid >> 1;   // 0..3 -> 32 rows each
    const int warp_n = wid & 1;    // 0..1 -> 64 cols each

    float acc[2][8][4];
    #pragma unroll
    for (int mi = 0; mi < 2; mi++)
        #pragma unroll
        for (int ni = 0; ni < 8; ni++)
            #pragma unroll
            for (int q = 0; q < 4; q++) acc[mi][ni][q] = 0.f;

    // tile-load index map: 4 float4 per thread for A and for B
    // A: f4id = tid + t*256; row = f4id>>3, kc = (f4id&7)*4
    // B: k = f4id>>5, nc = (f4id&31)*4

    // ---- prologue: k-tile 0 -> buffer 0 ----
    {
        #pragma unroll
        for (int t = 0; t < 4; t++) {
            const int f4 = tid + t * 256;
            const int row = f4 >> 3, kc = (f4 & 7) * 4;
            float4 a4 = make_float4(0.f, 0.f, 0.f, 0.f);
            const int arow = blockRow * 128 + row;
            if (arow < M)
                a4 = *reinterpret_cast<const float4*>(A + (size_t)arow * IN_DIM + kc);
            float* p = As + row * S1_AS_STRIDE + kc;
            p[0] = tf32r(a4.x); p[1] = tf32r(a4.y);
            p[2] = tf32r(a4.z); p[3] = tf32r(a4.w);
            const int bk = f4 >> 5, nc = (f4 & 31) * 4;
            float4 b4 = *reinterpret_cast<const float4*>(W1 + (size_t)bk * H_DIM + nc);
            float* q = Bs + bk * S1_BS_STRIDE + nc;
            q[0] = tf32r(b4.x); q[1] = tf32r(b4.y);
            q[2] = tf32r(b4.z); q[3] = tf32r(b4.w);
        }
    }
    __syncthreads();

    int cur = 0;
    constexpr int NKT = IN_DIM / 32;  // 8
    for (int kt = 0; kt < NKT; kt++) {
        float4 a_pref[4], b_pref[4];
        if (kt < NKT - 1) {
            const int k0 = (kt + 1) * 32;
            #pragma unroll
            for (int t = 0; t < 4; t++) {
                const int f4 = tid + t * 256;
                const int row = f4 >> 3, kc = (f4 & 7) * 4;
                const int arow = blockRow * 128 + row;
                a_pref[t] = make_float4(0.f, 0.f, 0.f, 0.f);
                if (arow < M)
                    a_pref[t] = *reinterpret_cast<const float4*>(
                        A + (size_t)arow * IN_DIM + k0 + kc);
                const int bk = f4 >> 5, nc = (f4 & 31) * 4;
                b_pref[t] = *reinterpret_cast<const float4*>(
                    W1 + (size_t)(k0 + bk) * H_DIM + nc);
            }
        }

        const float* Ac = As + cur * 128 * S1_AS_STRIDE;
        const float* Bc = Bs + cur * 32 * S1_BS_STRIDE;
        #pragma unroll
        for (int k8 = 0; k8 < 4; k8++) {
            const int kk = k8 * 8;
            uint32_t af[2][4];
            #pragma unroll
            for (int mi = 0; mi < 2; mi++) {
                const int rb = warp_m * 32 + mi * 16 + (lane >> 2);
                const int kc = kk + (lane & 3);
                af[mi][0] = __float_as_uint(Ac[rb * S1_AS_STRIDE + kc]);
                af[mi][1] = __float_as_uint(Ac[(rb + 8) * S1_AS_STRIDE + kc]);
                af[mi][2] = __float_as_uint(Ac[rb * S1_AS_STRIDE + kc + 4]);
                af[mi][3] = __float_as_uint(Ac[(rb + 8) * S1_AS_STRIDE + kc + 4]);
            }
            #pragma unroll
            for (int ni = 0; ni < 8; ni++) {
                const int nb = warp_n * 64 + ni * 8 + (lane >> 2);
                const uint32_t b0 =
                    __float_as_uint(Bc[(kk + (lane & 3)) * S1_BS_STRIDE + nb]);
                const uint32_t b1 =
                    __float_as_uint(Bc[(kk + 4 + (lane & 3)) * S1_BS_STRIDE + nb]);
                mma_tf32(acc[0][ni], af[0], b0, b1);
                mma_tf32(acc[1][ni], af[1], b0, b1);
            }
        }

        if (kt < NKT - 1) {
            const int nxt = 1 - cur;
            float* An = As + nxt * 128 * S1_AS_STRIDE;
            float* Bn = Bs + nxt * 32 * S1_BS_STRIDE;
            #pragma unroll
            for (int t = 0; t < 4; t++) {
                const int f4 = tid + t * 256;
                const int row = f4 >> 3, kc = (f4 & 7) * 4;
                float* p = An + row * S1_AS_STRIDE + kc;
                p[0] = tf32r(a_pref[t].x); p[1] = tf32r(a_pref[t].y);
                p[2] = tf32r(a_pref[t].z); p[3] = tf32r(a_pref[t].w);
                const int bk = f4 >> 5, nc = (f4 & 31) * 4;
                float* q = Bn + bk * S1_BS_STRIDE + nc;
                q[0] = tf32r(b_pref[t].x); q[1] = tf32r(b_pref[t].y);
                q[2] = tf32r(b_pref[t].z); q[3] = tf32r(b_pref[t].w);
            }
            __syncthreads();
            cur = nxt;
        }
    }

    // ---- stage 1 -> stage 2 transition ----
    __syncthreads();  // all warps done reading As/Bs before overlay

    float* H  = sm;            // [128][132]
    float* Ws = sm + 128 * S2_H_STRIDE;  // [128][44]

    // relu + tf32 + store h1 tile to smem
    #pragma unroll
    for (int mi = 0; mi < 2; mi++) {
        const int r0 = warp_m * 32 + mi * 16 + (lane >> 2);
        #pragma unroll
        for (int ni = 0; ni < 8; ni++) {
            const int c0 = warp_n * 64 + ni * 8 + 2 * (lane & 3);
            H[r0 * S2_H_STRIDE + c0]           = tf32r(fmaxf(acc[mi][ni][0], 0.f));
            H[r0 * S2_H_STRIDE + c0 + 1]       = tf32r(fmaxf(acc[mi][ni][1], 0.f));
            H[(r0 + 8) * S2_H_STRIDE + c0]     = tf32r(fmaxf(acc[mi][ni][2], 0.f));
            H[(r0 + 8) * S2_H_STRIDE + c0 + 1] = tf32r(fmaxf(acc[mi][ni][3], 0.f));
        }
    }
    // load W2 [128][40] -> Ws (tf32)
    for (int i = tid; i < H_DIM * C_DIM; i += 256)
        Ws[(i / C_DIM) * S2_W_STRIDE + (i % C_DIM)] = tf32r(W2[i]);
    __syncthreads();

    // ---- stage 2: h2 = H @ W2, each warp 16 rows, K=128 ----
    const int rb2 = wid * 16;
    float acc2[5][4];
    #pragma unroll
    for (int ni = 0; ni < 5; ni++)
        #pragma unroll
        for (int q = 0; q < 4; q++) acc2[ni][q] = 0.f;

    #pragma unroll
    for (int k8 = 0; k8 < 16; k8++) {
        const int kk = k8 * 8;
        uint32_t af[4];
        const int rr = rb2 + (lane >> 2);
        const int kc = kk + (lane & 3);
        af[0] = __float_as_uint(H[rr * S2_H_STRIDE + kc]);
        af[1] = __float_as_uint(H[(rr + 8) * S2_H_STRIDE + kc]);
        af[2] = __float_as_uint(H[rr * S2_H_STRIDE + kc + 4]);
        af[3] = __float_as_uint(H[(rr + 8) * S2_H_STRIDE + kc + 4]);
        #pragma unroll
        for (int ni = 0; ni < 5; ni++) {
            const int nb = ni * 8 + (lane >> 2);
            const uint32_t b0 =
                __float_as_uint(Ws[(kk + (lane & 3)) * S2_W_STRIDE + nb]);
            const uint32_t b1 =
                __float_as_uint(Ws[(kk + 4 + (lane & 3)) * S2_W_STRIDE + nb]);
            mma_tf32(acc2[ni], af, b0, b1);
        }
    }

    // store h2 tile
    const int row0 = blockRow * 128 + rb2 + (lane >> 2);
    #pragma unroll
    for (int ni = 0; ni < 5; ni++) {
        const int c0 = ni * 8 + 2 * (lane & 3);
        if (row0 < M) {
            float2 v = make_float2(acc2[ni][0], acc2[ni][1]);
            *reinterpret_cast<float2*>(g_h2 + (size_t)row0 * C_DIM + c0) = v;
        }
        if (row0 + 8 < M) {
            float2 v = make_float2(acc2[ni][2], acc2[ni][3]);
            *reinterpret_cast<float2*>(g_h2 + (size_t)(row0 + 8) * C_DIM + c0) = v;
        }
    }
}

// ---------------------------------------------------------------------------
// SPMM: out[dst] += val * x[src], COO with SORTED dst.
// 320 threads = 32 groups x 10 lanes; each lane owns a float4 (4 columns).
// Register accumulation across equal-dst runs; atomic flush on dst change.
// Metadata software-pipelined one edge ahead.
// ---------------------------------------------------------------------------
#define SPMM_CHUNK 2048
#define SPMM_G 64

__global__ __launch_bounds__(320) void spmm_kernel(
    const int* __restrict__ src, const int* __restrict__ dst,
    const float* __restrict__ val, const float* __restrict__ x,
    float* __restrict__ out, int E) {
    __shared__ int   s_src[SPMM_CHUNK];
    __shared__ int   s_dst[SPMM_CHUNK];
    __shared__ float s_val[SPMM_CHUNK];

    const int tid = threadIdx.x;
    const int e0 = blockIdx.x * SPMM_CHUNK;
    const int cnt = min(SPMM_CHUNK, E - e0);

    for (int i = tid; i < cnt; i += 320) {
        s_src[i] = src[e0 + i];
        s_dst[i] = dst[e0 + i];
        s_val[i] = val[e0 + i];
    }
    __syncthreads();

    const int g = tid / 10;
    const int lane = tid % 10;
    const int begin = g * SPMM_G;
    const int end = min(begin + SPMM_G, cnt);
    if (begin < end) {
        float ax = 0.f, ay = 0.f, az = 0.f, aw = 0.f;
        int prev = s_dst[begin];
        int curS = s_src[begin];
        int curD = prev;
        float curV = s_val[begin];
        for (int i = begin; i < end; i++) {
            const int cs = curS;
            const int cd = curD;
            const float cv = curV;
            const float4 xv = *reinterpret_cast<const float4*>(
                x + (size_t)cs * C_DIM + lane * 4);
            if (i + 1 < end) {
                curS = s_src[i + 1];
                curD = s_dst[i + 1];
                curV = s_val[i + 1];
            }
            if (cd != prev) {
                float* o = out + (size_t)prev * C_DIM + lane * 4;
                atomicAdd(o + 0, ax); atomicAdd(o + 1, ay);
                atomicAdd(o + 2, az); atomicAdd(o + 3, aw);
                ax = ay = az = aw = 0.f;
                prev = cd;
            }
            ax = fmaf(cv, xv.x, ax); ay = fmaf(cv, xv.y, ay);
            az = fmaf(cv, xv.z, az); aw = fmaf(cv, xv.w, aw);
        }
        float* o = out + (size_t)prev * C_DIM + lane * 4;
        atomicAdd(o + 0, ax); atomicAdd(o + 1, ay);
        atomicAdd(o + 2, az); atomicAdd(o + 3, aw);
    }
}

extern "C" void kernel_launch(void* const* d_in, const int* in_sizes, int n_in,
                              void* d_out, int out_size) {
    const float* features = (const float*)d_in[0];
    const float* W1       = (const float*)d_in[1];
    const float* W2       = (const float*)d_in[2];
    const int*   edge_src = (const int*)d_in[3];
    const int*   edge_dst = (const int*)d_in[4];
    const float* edge_val = (const float*)d_in[5];
    float* out = (float*)d_out;

    const int M = in_sizes[0] / IN_DIM;   // 100000
    const int E = in_sizes[3];            // 1600000

    float *p_h2, *p_z1;
    cudaGetSymbolAddress((void**)&p_h2, g_h2);
    cudaGetSymbolAddress((void**)&p_z1, g_z1);

    static bool attr_set = false;
    if (!attr_set) {
        cudaFuncSetAttribute(fused_mlp_kernel,
                             cudaFuncAttributeMaxDynamicSharedMemorySize,
                             FUSED_SMEM_BYTES);
        attr_set = true;
    }

    // 1) h2 = relu(X @ W1) @ W2  (single fused kernel)
    fused_mlp_kernel<<<(M + 127) / 128, 256, FUSED_SMEM_BYTES>>>(
        features, W1, W2, M);

    const size_t zbytes = (size_t)M * C_DIM * sizeof(float);
    // 2) z1 = A @ h2
    cudaMemsetAsync(p_z1, 0, zbytes);
    spmm_kernel<<<(E + SPMM_CHUNK - 1) / SPMM_CHUNK, 320>>>(
        edge_src, edge_dst, edge_val, p_h2, p_z1, E);
    // 3) out = A @ z1
    cudaMemsetAsync(out, 0, zbytes);
    spmm_kernel<<<(E + SPMM_CHUNK - 1) / SPMM_CHUNK, 320>>>(
        edge_src, edge_dst, edge_val, p_z1, out, E);
}

// round 4
// speedup vs baseline: 2.5239x; 1.2010x over previous
#include <cuda_runtime.h>
#include <cstddef>
#include <cstdint>

#define NN 100000
#define IN_DIM 256
#define H_DIM 128
#define C_DIM 40

// Scratch (device globals — no allocation allowed)
__device__ float g_h2[(size_t)NN * C_DIM];   // (relu(X@W1))@W2
__device__ float g_z1[(size_t)NN * C_DIM];   // first propagation
__device__ int   g_rowptr[NN + 1];           // CSR offsets from sorted edge_dst

// ---------------------------------------------------------------------------
// tf32 helpers
// ---------------------------------------------------------------------------
__device__ __forceinline__ float tf32r(float x) {
    uint32_t u;
    asm("cvt.rna.tf32.f32 %0, %1;" : "=r"(u) : "f"(x));
    return __uint_as_float(u);
}

__device__ __forceinline__ void mma_tf32(float* c, const uint32_t* a,
                                         uint32_t b0, uint32_t b1) {
    asm volatile(
        "mma.sync.aligned.m16n8k8.row.col.f32.tf32.tf32.f32 "
        "{%0,%1,%2,%3}, {%4,%5,%6,%7}, {%8,%9}, {%0,%1,%2,%3};\n"
        : "+f"(c[0]), "+f"(c[1]), "+f"(c[2]), "+f"(c[3])
        : "r"(a[0]), "r"(a[1]), "r"(a[2]), "r"(a[3]), "r"(b0), "r"(b1));
}

// ---------------------------------------------------------------------------
// Fused MLP: g_h2 = relu(X[M,256] @ W1[256,128]) @ W2[128,40]
// (unchanged from round 3)
// ---------------------------------------------------------------------------
#define S1_AS_STRIDE 36
#define S1_BS_STRIDE 132
#define S2_H_STRIDE 132
#define S2_W_STRIDE 44
#define FUSED_SMEM_BYTES 90112

extern __shared__ float sm[];

__global__ __launch_bounds__(256) void fused_mlp_kernel(
    const float* __restrict__ A, const float* __restrict__ W1,
    const float* __restrict__ W2, int M) {
    const int tid = threadIdx.x;
    const int lane = tid & 31;
    const int wid = tid >> 5;
    const int blockRow = blockIdx.x;

    float* As = sm;                           // [2][128][36]
    float* Bs = sm + 2 * 128 * S1_AS_STRIDE;  // [2][32][132]

    const int warp_m = wid >> 1;   // 0..3 -> 32 rows each
    const int warp_n = wid & 1;    // 0..1 -> 64 cols each

    float acc[2][8][4];
    #pragma unroll
    for (int mi = 0; mi < 2; mi++)
        #pragma unroll
        for (int ni = 0; ni < 8; ni++)
            #pragma unroll
            for (int q = 0; q < 4; q++) acc[mi][ni][q] = 0.f;

    // ---- prologue: k-tile 0 -> buffer 0 ----
    {
        #pragma unroll
        for (int t = 0; t < 4; t++) {
            const int f4 = tid + t * 256;
            const int row = f4 >> 3, kc = (f4 & 7) * 4;
            float4 a4 = make_float4(0.f, 0.f, 0.f, 0.f);
            const int arow = blockRow * 128 + row;
            if (arow < M)
                a4 = *reinterpret_cast<const float4*>(A + (size_t)arow * IN_DIM + kc);
            float* p = As + row * S1_AS_STRIDE + kc;
            p[0] = tf32r(a4.x); p[1] = tf32r(a4.y);
            p[2] = tf32r(a4.z); p[3] = tf32r(a4.w);
            const int bk = f4 >> 5, nc = (f4 & 31) * 4;
            float4 b4 = *reinterpret_cast<const float4*>(W1 + (size_t)bk * H_DIM + nc);
            float* q = Bs + bk * S1_BS_STRIDE + nc;
            q[0] = tf32r(b4.x); q[1] = tf32r(b4.y);
            q[2] = tf32r(b4.z); q[3] = tf32r(b4.w);
        }
    }
    __syncthreads();

    int cur = 0;
    constexpr int NKT = IN_DIM / 32;  // 8
    for (int kt = 0; kt < NKT; kt++) {
        float4 a_pref[4], b_pref[4];
        if (kt < NKT - 1) {
            const int k0 = (kt + 1) * 32;
            #pragma unroll
            for (int t = 0; t < 4; t++) {
                const int f4 = tid + t * 256;
                const int row = f4 >> 3, kc = (f4 & 7) * 4;
                const int arow = blockRow * 128 + row;
                a_pref[t] = make_float4(0.f, 0.f, 0.f, 0.f);
                if (arow < M)
                    a_pref[t] = *reinterpret_cast<const float4*>(
                        A + (size_t)arow * IN_DIM + k0 + kc);
                const int bk = f4 >> 5, nc = (f4 & 31) * 4;
                b_pref[t] = *reinterpret_cast<const float4*>(
                    W1 + (size_t)(k0 + bk) * H_DIM + nc);
            }
        }

        const float* Ac = As + cur * 128 * S1_AS_STRIDE;
        const float* Bc = Bs + cur * 32 * S1_BS_STRIDE;
        #pragma unroll
        for (int k8 = 0; k8 < 4; k8++) {
            const int kk = k8 * 8;
            uint32_t af[2][4];
            #pragma unroll
            for (int mi = 0; mi < 2; mi++) {
                const int rb = warp_m * 32 + mi * 16 + (lane >> 2);
                const int kc = kk + (lane & 3);
                af[mi][0] = __float_as_uint(Ac[rb * S1_AS_STRIDE + kc]);
                af[mi][1] = __float_as_uint(Ac[(rb + 8) * S1_AS_STRIDE + kc]);
                af[mi][2] = __float_as_uint(Ac[rb * S1_AS_STRIDE + kc + 4]);
                af[mi][3] = __float_as_uint(Ac[(rb + 8) * S1_AS_STRIDE + kc + 4]);
            }
            #pragma unroll
            for (int ni = 0; ni < 8; ni++) {
                const int nb = warp_n * 64 + ni * 8 + (lane >> 2);
                const uint32_t b0 =
                    __float_as_uint(Bc[(kk + (lane & 3)) * S1_BS_STRIDE + nb]);
                const uint32_t b1 =
                    __float_as_uint(Bc[(kk + 4 + (lane & 3)) * S1_BS_STRIDE + nb]);
                mma_tf32(acc[0][ni], af[0], b0, b1);
                mma_tf32(acc[1][ni], af[1], b0, b1);
            }
        }

        if (kt < NKT - 1) {
            const int nxt = 1 - cur;
            float* An = As + nxt * 128 * S1_AS_STRIDE;
            float* Bn = Bs + nxt * 32 * S1_BS_STRIDE;
            #pragma unroll
            for (int t = 0; t < 4; t++) {
                const int f4 = tid + t * 256;
                const int row = f4 >> 3, kc = (f4 & 7) * 4;
                float* p = An + row * S1_AS_STRIDE + kc;
                p[0] = tf32r(a_pref[t].x); p[1] = tf32r(a_pref[t].y);
                p[2] = tf32r(a_pref[t].z); p[3] = tf32r(a_pref[t].w);
                const int bk = f4 >> 5, nc = (f4 & 31) * 4;
                float* q = Bn + bk * S1_BS_STRIDE + nc;
                q[0] = tf32r(b_pref[t].x); q[1] = tf32r(b_pref[t].y);
                q[2] = tf32r(b_pref[t].z); q[3] = tf32r(b_pref[t].w);
            }
            __syncthreads();
            cur = nxt;
        }
    }

    // ---- stage 1 -> stage 2 transition ----
    __syncthreads();

    float* H  = sm;                      // [128][132]
    float* Ws = sm + 128 * S2_H_STRIDE;  // [128][44]

    #pragma unroll
    for (int mi = 0; mi < 2; mi++) {
        const int r0 = warp_m * 32 + mi * 16 + (lane >> 2);
        #pragma unroll
        for (int ni = 0; ni < 8; ni++) {
            const int c0 = warp_n * 64 + ni * 8 + 2 * (lane & 3);
            H[r0 * S2_H_STRIDE + c0]           = tf32r(fmaxf(acc[mi][ni][0], 0.f));
            H[r0 * S2_H_STRIDE + c0 + 1]       = tf32r(fmaxf(acc[mi][ni][1], 0.f));
            H[(r0 + 8) * S2_H_STRIDE + c0]     = tf32r(fmaxf(acc[mi][ni][2], 0.f));
            H[(r0 + 8) * S2_H_STRIDE + c0 + 1] = tf32r(fmaxf(acc[mi][ni][3], 0.f));
        }
    }
    for (int i = tid; i < H_DIM * C_DIM; i += 256)
        Ws[(i / C_DIM) * S2_W_STRIDE + (i % C_DIM)] = tf32r(W2[i]);
    __syncthreads();

    const int rb2 = wid * 16;
    float acc2[5][4];
    #pragma unroll
    for (int ni = 0; ni < 5; ni++)
        #pragma unroll
        for (int q = 0; q < 4; q++) acc2[ni][q] = 0.f;

    #pragma unroll
    for (int k8 = 0; k8 < 16; k8++) {
        const int kk = k8 * 8;
        uint32_t af[4];
        const int rr = rb2 + (lane >> 2);
        const int kc = kk + (lane & 3);
        af[0] = __float_as_uint(H[rr * S2_H_STRIDE + kc]);
        af[1] = __float_as_uint(H[(rr + 8) * S2_H_STRIDE + kc]);
        af[2] = __float_as_uint(H[rr * S2_H_STRIDE + kc + 4]);
        af[3] = __float_as_uint(H[(rr + 8) * S2_H_STRIDE + kc + 4]);
        #pragma unroll
        for (int ni = 0; ni < 5; ni++) {
            const int nb = ni * 8 + (lane >> 2);
            const uint32_t b0 =
                __float_as_uint(Ws[(kk + (lane & 3)) * S2_W_STRIDE + nb]);
            const uint32_t b1 =
                __float_as_uint(Ws[(kk + 4 + (lane & 3)) * S2_W_STRIDE + nb]);
            mma_tf32(acc2[ni], af, b0, b1);
        }
    }

    const int row0 = blockRow * 128 + rb2 + (lane >> 2);
    #pragma unroll
    for (int ni = 0; ni < 5; ni++) {
        const int c0 = ni * 8 + 2 * (lane & 3);
        if (row0 < M) {
            float2 v = make_float2(acc2[ni][0], acc2[ni][1]);
            *reinterpret_cast<float2*>(g_h2 + (size_t)row0 * C_DIM + c0) = v;
        }
        if (row0 + 8 < M) {
            float2 v = make_float2(acc2[ni][2], acc2[ni][3]);
            *reinterpret_cast<float2*>(g_h2 + (size_t)(row0 + 8) * C_DIM + c0) = v;
        }
    }
}

// ---------------------------------------------------------------------------
// Row-pointer build: edge_dst is SORTED. rowptr[v] = lower_bound(dst, v).
// One thread per v in [0, N]; 21-step binary search (L2-resident dst array).
// ---------------------------------------------------------------------------
__global__ void rowptr_kernel(const int* __restrict__ dst, int N, int E) {
    const int v = blockIdx.x * blockDim.x + threadIdx.x;
    if (v > N) return;
    int lo = 0, hi = E;
    while (lo < hi) {
        const int mid = (lo + hi) >> 1;
        if (__ldg(dst + mid) < v) lo = mid + 1; else hi = mid;
    }
    g_rowptr[v] = lo;
}

// ---------------------------------------------------------------------------
// CSR SPMM: out[v] = sum_{i in [rowptr[v], rowptr[v+1])} val[i] * x[src[i]]
// 320 threads = 32 groups x 10 lanes; group owns one node; lane owns float4.
// No atomics, no output zeroing, 2-way unrolled independent gathers.
// ---------------------------------------------------------------------------
__global__ __launch_bounds__(320) void spmm_csr_kernel(
    const int* __restrict__ src, const float* __restrict__ val,
    const float* __restrict__ x, float* __restrict__ out, int N) {
    const int tid = threadIdx.x;
    const int node = blockIdx.x * 32 + tid / 10;
    const int lane = tid % 10;
    if (node >= N) return;

    const int start = __ldg(g_rowptr + node);
    const int end   = __ldg(g_rowptr + node + 1);

    float4 a0 = make_float4(0.f, 0.f, 0.f, 0.f);
    float4 a1 = make_float4(0.f, 0.f, 0.f, 0.f);

    int i = start;
    for (; i + 2 <= end; i += 2) {
        const int   s0 = __ldg(src + i);
        const int   s1 = __ldg(src + i + 1);
        const float v0 = __ldg(val + i);
        const float v1 = __ldg(val + i + 1);
        const float4 x0 = *reinterpret_cast<const float4*>(
            x + (size_t)s0 * C_DIM + lane * 4);
        const float4 x1 = *reinterpret_cast<const float4*>(
            x + (size_t)s1 * C_DIM + lane * 4);
        a0.x = fmaf(v0, x0.x, a0.x); a0.y = fmaf(v0, x0.y, a0.y);
        a0.z = fmaf(v0, x0.z, a0.z); a0.w = fmaf(v0, x0.w, a0.w);
        a1.x = fmaf(v1, x1.x, a1.x); a1.y = fmaf(v1, x1.y, a1.y);
        a1.z = fmaf(v1, x1.z, a1.z); a1.w = fmaf(v1, x1.w, a1.w);
    }
    if (i < end) {
        const int   s0 = __ldg(src + i);
        const float v0 = __ldg(val + i);
        const float4 x0 = *reinterpret_cast<const float4*>(
            x + (size_t)s0 * C_DIM + lane * 4);
        a0.x = fmaf(v0, x0.x, a0.x); a0.y = fmaf(v0, x0.y, a0.y);
        a0.z = fmaf(v0, x0.z, a0.z); a0.w = fmaf(v0, x0.w, a0.w);
    }

    float4 r;
    r.x = a0.x + a1.x; r.y = a0.y + a1.y;
    r.z = a0.z + a1.z; r.w = a0.w + a1.w;
    *reinterpret_cast<float4*>(out + (size_t)node * C_DIM + lane * 4) = r;
}

extern "C" void kernel_launch(void* const* d_in, const int* in_sizes, int n_in,
                              void* d_out, int out_size) {
    const float* features = (const float*)d_in[0];
    const float* W1       = (const float*)d_in[1];
    const float* W2       = (const float*)d_in[2];
    const int*   edge_src = (const int*)d_in[3];
    const int*   edge_dst = (const int*)d_in[4];
    const float* edge_val = (const float*)d_in[5];
    float* out = (float*)d_out;

    const int M = in_sizes[0] / IN_DIM;   // 100000
    const int E = in_sizes[3];            // 1600000

    float *p_h2, *p_z1;
    cudaGetSymbolAddress((void**)&p_h2, g_h2);
    cudaGetSymbolAddress((void**)&p_z1, g_z1);

    static bool attr_set = false;
    if (!attr_set) {
        cudaFuncSetAttribute(fused_mlp_kernel,
                             cudaFuncAttributeMaxDynamicSharedMemorySize,
                             FUSED_SMEM_BYTES);
        attr_set = true;
    }

    // 1) h2 = relu(X @ W1) @ W2  (single fused kernel)
    fused_mlp_kernel<<<(M + 127) / 128, 256, FUSED_SMEM_BYTES>>>(
        features, W1, W2, M);

    // 2) CSR row pointers from sorted edge_dst (shared by both propagations;
    //    overlaps with fused_mlp in-stream? no — same stream, but it's cheap)
    rowptr_kernel<<<(M + 257) / 256, 256>>>(edge_dst, M, E);

    // 3) z1 = A @ h2 ; out = A @ z1   (no zeroing, no atomics)
    spmm_csr_kernel<<<(M + 31) / 32, 320>>>(edge_src, edge_val, p_h2, p_z1, M);
    spmm_csr_kernel<<<(M + 31) / 32, 320>>>(edge_src, edge_val, p_z1, out, M);
}